// round 1
// baseline (speedup 1.0000x reference)
#include <cuda_runtime.h>

// Problem constants (shapes fixed by the dataset)
#define NPTS 65536
#define TJ   2048                 // pc1 points per j-slice (one smem tile)
#define G1   (NPTS / TJ)          // 32 j-slices
#define PTSB 256                  // pc0 points per block (128 threads x 2)
#define G0   (NPTS / PTSB)        // 256 pc0 chunks
#define RB   256                  // reduce blocks

// Scratch (no allocations allowed -> __device__ globals)
__device__ float g_pack[NPTS * 4];        // 1 MB: per 4-j group: x[4],y[4],z[4],bsq[4]
__device__ float g_partial[G1 * NPTS];    // 8 MB partial mins (excluding ||a||^2)
__device__ float g_block[RB * 2];         // per-block (sum, count)

typedef unsigned long long u64;

__device__ __forceinline__ u64 fma2(u64 a, u64 b, u64 c) {
    u64 d;
    asm("fma.rn.f32x2 %0, %1, %2, %3;" : "=l"(d) : "l"(a), "l"(b), "l"(c));
    return d;
}
__device__ __forceinline__ u64 pack2(float x, float y) {
    u64 d;
    asm("mov.b64 %0, {%1, %2};" : "=l"(d) : "f"(x), "f"(y));
    return d;
}
__device__ __forceinline__ float2 unpack2(u64 v) {
    float2 r;
    asm("mov.b64 {%0, %1}, %2;" : "=f"(r.x), "=f"(r.y) : "l"(v));
    return r;
}

// ---------------------------------------------------------------------------
// K1: pack pc1 into 4-j groups: (x0..x3)(y0..y3)(z0..z3)(bsq0..bsq3)
// ---------------------------------------------------------------------------
__global__ void pack_k(const float* __restrict__ pc1) {
    int q = blockIdx.x * blockDim.x + threadIdx.x;
    if (q >= NPTS / 4) return;
    float x[4], y[4], z[4], s[4];
#pragma unroll
    for (int k = 0; k < 4; k++) {
        const float* p = pc1 + 3 * (q * 4 + k);
        x[k] = p[0]; y[k] = p[1]; z[k] = p[2];
        s[k] = x[k] * x[k] + y[k] * y[k] + z[k] * z[k];
    }
    float4* o = (float4*)(g_pack + (size_t)q * 16);
    o[0] = make_float4(x[0], x[1], x[2], x[3]);
    o[1] = make_float4(y[0], y[1], y[2], y[3]);
    o[2] = make_float4(z[0], z[1], z[2], z[3]);
    o[3] = make_float4(s[0], s[1], s[2], s[3]);
}

// ---------------------------------------------------------------------------
// K2: main. Each block: 256 pc0 points x one 2048-j slice.
// Each thread holds 2 pc0 points (a0, a1) as packed (-2a, -2a) f32x2 operands.
// Inner loop per 4-j group: 4x LDS.128, 12x fma.f32x2, 8x FMNMX.
// t = bsq - 2 a.b  (min over j); ||a||^2 added in the reduce kernel.
// ---------------------------------------------------------------------------
__global__ void __launch_bounds__(128, 4) nn_k(const float* __restrict__ pc0) {
    __shared__ float4 sm[(TJ / 4) * 4];   // 2048 float4 = 32 KB

    int g0 = blockIdx.x >> 5;             // / G1
    int g1 = blockIdx.x & (G1 - 1);
    int tid = threadIdx.x;

    // cooperative smem fill (slice of g_pack, L2-resident)
    const float4* src = ((const float4*)g_pack) + (size_t)g1 * (TJ / 4) * 4;
#pragma unroll
    for (int t = 0; t < 16; t++)
        sm[tid + t * 128] = src[tid + t * 128];

    int i0 = g0 * PTSB + tid;
    int i1 = i0 + 128;
    float a0x = pc0[3 * i0], a0y = pc0[3 * i0 + 1], a0z = pc0[3 * i0 + 2];
    float a1x = pc0[3 * i1], a1y = pc0[3 * i1 + 1], a1z = pc0[3 * i1 + 2];
    u64 A0X = pack2(-2.f * a0x, -2.f * a0x);
    u64 A0Y = pack2(-2.f * a0y, -2.f * a0y);
    u64 A0Z = pack2(-2.f * a0z, -2.f * a0z);
    u64 A1X = pack2(-2.f * a1x, -2.f * a1x);
    u64 A1Y = pack2(-2.f * a1y, -2.f * a1y);
    u64 A1Z = pack2(-2.f * a1z, -2.f * a1z);

    __syncthreads();

    float m00 = 1e30f, m01 = 1e30f, m10 = 1e30f, m11 = 1e30f;

#pragma unroll 2
    for (int q = 0; q < TJ / 4; q++) {
        float4 BX = sm[4 * q + 0];
        float4 BY = sm[4 * q + 1];
        float4 BZ = sm[4 * q + 2];
        float4 BS = sm[4 * q + 3];
        {   // j pair 0,1
            u64 bx = pack2(BX.x, BX.y), by = pack2(BY.x, BY.y);
            u64 bz = pack2(BZ.x, BZ.y), bs = pack2(BS.x, BS.y);
            u64 t0 = fma2(A0X, bx, fma2(A0Y, by, fma2(A0Z, bz, bs)));
            u64 t1 = fma2(A1X, bx, fma2(A1Y, by, fma2(A1Z, bz, bs)));
            float2 u0 = unpack2(t0), u1 = unpack2(t1);
            m00 = fminf(m00, u0.x); m01 = fminf(m01, u0.y);
            m10 = fminf(m10, u1.x); m11 = fminf(m11, u1.y);
        }
        {   // j pair 2,3
            u64 bx = pack2(BX.z, BX.w), by = pack2(BY.z, BY.w);
            u64 bz = pack2(BZ.z, BZ.w), bs = pack2(BS.z, BS.w);
            u64 t0 = fma2(A0X, bx, fma2(A0Y, by, fma2(A0Z, bz, bs)));
            u64 t1 = fma2(A1X, bx, fma2(A1Y, by, fma2(A1Z, bz, bs)));
            float2 u0 = unpack2(t0), u1 = unpack2(t1);
            m00 = fminf(m00, u0.x); m01 = fminf(m01, u0.y);
            m10 = fminf(m10, u1.x); m11 = fminf(m11, u1.y);
        }
    }

    g_partial[(size_t)g1 * NPTS + i0] = fminf(m00, m01);
    g_partial[(size_t)g1 * NPTS + i1] = fminf(m10, m11);
}

// ---------------------------------------------------------------------------
// K3: per-point min over the 32 slices, add ||a||^2, mask, block-sum.
// ---------------------------------------------------------------------------
__global__ void reduce_k(const float* __restrict__ pc0) {
    int tid = threadIdx.x;
    int i = blockIdx.x * 256 + tid;
    float m = 1e30f;
#pragma unroll
    for (int g = 0; g < G1; g++)
        m = fminf(m, g_partial[(size_t)g * NPTS + i]);
    float x = pc0[3 * i], y = pc0[3 * i + 1], z = pc0[3 * i + 2];
    float d = fmaf(x, x, fmaf(y, y, z * z)) + m;
    float s = 0.f, c = 0.f;
    if (d <= 2.0f) { s = d; c = 1.0f; }

    __shared__ float ss[256], sc[256];
    ss[tid] = s; sc[tid] = c;
    __syncthreads();
    for (int o = 128; o > 0; o >>= 1) {
        if (tid < o) { ss[tid] += ss[tid + o]; sc[tid] += sc[tid + o]; }
        __syncthreads();
    }
    if (tid == 0) {
        g_block[2 * blockIdx.x + 0] = ss[0];
        g_block[2 * blockIdx.x + 1] = sc[0];
    }
}

// ---------------------------------------------------------------------------
// K4: deterministic final reduction -> scalar mean
// ---------------------------------------------------------------------------
__global__ void final_k(float* __restrict__ out) {
    int tid = threadIdx.x;
    __shared__ float ss[256], sc[256];
    ss[tid] = g_block[2 * tid + 0];
    sc[tid] = g_block[2 * tid + 1];
    __syncthreads();
    for (int o = 128; o > 0; o >>= 1) {
        if (tid < o) { ss[tid] += ss[tid + o]; sc[tid] += sc[tid + o]; }
        __syncthreads();
    }
    if (tid == 0) out[0] = ss[0] / sc[0];
}

extern "C" void kernel_launch(void* const* d_in, const int* in_sizes, int n_in,
                              void* d_out, int out_size) {
    const float* pc0 = (const float*)d_in[0];
    const float* pc1 = (const float*)d_in[1];
    (void)in_sizes; (void)n_in; (void)out_size;

    pack_k<<<(NPTS / 4) / 128, 128>>>(pc1);
    nn_k<<<G0 * G1, 128>>>(pc0);
    reduce_k<<<RB, 256>>>(pc0);
    final_k<<<1, 256>>>((float*)d_out);
}

// round 2
// speedup vs baseline: 1.0499x; 1.0499x over previous
#include <cuda_runtime.h>

// Problem constants (shapes fixed by the dataset)
#define NPTS 65536
#define TJ   2048                 // pc1 points per j-slice (one smem tile)
#define G1   (NPTS / TJ)          // 32 j-slices
#define APT  4                    // pc0 points per thread
#define PTSB (128 * APT)          // 512 pc0 points per block
#define G0   (NPTS / PTSB)        // 128 pc0 chunks
#define RB   256                  // reduce blocks

// Scratch (no allocations allowed -> __device__ globals)
__device__ float g_pack[NPTS * 4];        // 1 MB: per 4-j group: x[4],y[4],z[4],bsq[4]
__device__ float g_partial[G1 * NPTS];    // 8 MB partial mins (excluding ||a||^2)
__device__ float g_block[RB * 2];         // per-block (sum, count)

typedef unsigned long long u64;

__device__ __forceinline__ u64 fma2(u64 a, u64 b, u64 c) {
    u64 d;
    asm("fma.rn.f32x2 %0, %1, %2, %3;" : "=l"(d) : "l"(a), "l"(b), "l"(c));
    return d;
}
__device__ __forceinline__ u64 pack2(float x, float y) {
    u64 d;
    asm("mov.b64 %0, {%1, %2};" : "=l"(d) : "f"(x), "f"(y));
    return d;
}
__device__ __forceinline__ void unpack2(u64 v, float& lo, float& hi) {
    asm("mov.b64 {%0, %1}, %2;" : "=f"(lo), "=f"(hi) : "l"(v));
}
// 16B vector load from shared: yields two packed f32x2 operands directly (no MOVs)
__device__ __forceinline__ void lds2x64(unsigned addr, u64& a, u64& b) {
    asm("ld.shared.v2.b64 {%0, %1}, [%2];" : "=l"(a), "=l"(b) : "r"(addr));
}

// ---------------------------------------------------------------------------
// K1: pack pc1 into 4-j groups: (x0..x3)(y0..y3)(z0..z3)(bsq0..bsq3)
// ---------------------------------------------------------------------------
__global__ void pack_k(const float* __restrict__ pc1) {
    int q = blockIdx.x * blockDim.x + threadIdx.x;
    if (q >= NPTS / 4) return;
    float x[4], y[4], z[4], s[4];
#pragma unroll
    for (int k = 0; k < 4; k++) {
        const float* p = pc1 + 3 * (q * 4 + k);
        x[k] = p[0]; y[k] = p[1]; z[k] = p[2];
        s[k] = x[k] * x[k] + y[k] * y[k] + z[k] * z[k];
    }
    float4* o = (float4*)(g_pack + (size_t)q * 16);
    o[0] = make_float4(x[0], x[1], x[2], x[3]);
    o[1] = make_float4(y[0], y[1], y[2], y[3]);
    o[2] = make_float4(z[0], z[1], z[2], z[3]);
    o[3] = make_float4(s[0], s[1], s[2], s[3]);
}

// ---------------------------------------------------------------------------
// K2: main. Each block: 512 pc0 points x one 2048-j slice.
// Each thread holds 4 pc0 points as packed (-2a,-2a) f32x2 operands.
// Per 4-j group per thread: 4x LDS.v2.b64, 24x fma.f32x2, 16x FMNMX.
// t = bsq - 2 a.b  (min over j); ||a||^2 added in the reduce kernel.
// ---------------------------------------------------------------------------
__global__ void __launch_bounds__(128, 4) nn_k(const float* __restrict__ pc0) {
    __shared__ __align__(16) float4 sm[(TJ / 4) * 4];   // 2048 float4 = 32 KB

    int g0 = (int)blockIdx.x >> 5;             // / G1
    int g1 = (int)blockIdx.x & (G1 - 1);
    int tid = threadIdx.x;

    // cooperative smem fill (slice of g_pack, L2-resident)
    const float4* src = ((const float4*)g_pack) + (size_t)g1 * (TJ / 4) * 4;
#pragma unroll
    for (int t = 0; t < 16; t++)
        sm[tid + t * 128] = src[tid + t * 128];

    // load 4 pc0 points, build duplicated (-2a,-2a) packed operands
    u64 AX[APT], AY[APT], AZ[APT];
    int ib = g0 * PTSB + tid;
#pragma unroll
    for (int a = 0; a < APT; a++) {
        int i = ib + a * 128;
        float x = pc0[3 * i], y = pc0[3 * i + 1], z = pc0[3 * i + 2];
        AX[a] = pack2(-2.f * x, -2.f * x);
        AY[a] = pack2(-2.f * y, -2.f * y);
        AZ[a] = pack2(-2.f * z, -2.f * z);
    }

    unsigned sbase;
    asm("{ .reg .u64 t; cvta.to.shared.u64 t, %1; cvt.u32.u64 %0, t; }"
        : "=r"(sbase) : "l"(sm));

    __syncthreads();

    float mlo[APT], mhi[APT];
#pragma unroll
    for (int a = 0; a < APT; a++) { mlo[a] = 1e30f; mhi[a] = 1e30f; }

#pragma unroll 2
    for (int q = 0; q < TJ / 4; q++) {
        unsigned ad = sbase + q * 64u;
        u64 bx01, bx23, by01, by23, bz01, bz23, bs01, bs23;
        lds2x64(ad +  0u, bx01, bx23);
        lds2x64(ad + 16u, by01, by23);
        lds2x64(ad + 32u, bz01, bz23);
        lds2x64(ad + 48u, bs01, bs23);
#pragma unroll
        for (int a = 0; a < APT; a++) {
            u64 t01 = fma2(AX[a], bx01, fma2(AY[a], by01, fma2(AZ[a], bz01, bs01)));
            u64 t23 = fma2(AX[a], bx23, fma2(AY[a], by23, fma2(AZ[a], bz23, bs23)));
            float l0, h0, l1, h1;
            unpack2(t01, l0, h0);
            unpack2(t23, l1, h1);
            mlo[a] = fminf(mlo[a], l0);
            mhi[a] = fminf(mhi[a], h0);
            mlo[a] = fminf(mlo[a], l1);
            mhi[a] = fminf(mhi[a], h1);
        }
    }

    float* dst = g_partial + (size_t)g1 * NPTS + ib;
#pragma unroll
    for (int a = 0; a < APT; a++)
        dst[a * 128] = fminf(mlo[a], mhi[a]);
}

// ---------------------------------------------------------------------------
// K3: per-point min over the 32 slices, add ||a||^2, mask, block-sum.
// ---------------------------------------------------------------------------
__global__ void reduce_k(const float* __restrict__ pc0) {
    int tid = threadIdx.x;
    int i = blockIdx.x * 256 + tid;
    float m = 1e30f;
#pragma unroll
    for (int g = 0; g < G1; g++)
        m = fminf(m, g_partial[(size_t)g * NPTS + i]);
    float x = pc0[3 * i], y = pc0[3 * i + 1], z = pc0[3 * i + 2];
    float d = fmaf(x, x, fmaf(y, y, z * z)) + m;
    float s = 0.f, c = 0.f;
    if (d <= 2.0f) { s = d; c = 1.0f; }

    __shared__ float ss[256], sc[256];
    ss[tid] = s; sc[tid] = c;
    __syncthreads();
    for (int o = 128; o > 0; o >>= 1) {
        if (tid < o) { ss[tid] += ss[tid + o]; sc[tid] += sc[tid + o]; }
        __syncthreads();
    }
    if (tid == 0) {
        g_block[2 * blockIdx.x + 0] = ss[0];
        g_block[2 * blockIdx.x + 1] = sc[0];
    }
}

// ---------------------------------------------------------------------------
// K4: deterministic final reduction -> scalar mean
// ---------------------------------------------------------------------------
__global__ void final_k(float* __restrict__ out) {
    int tid = threadIdx.x;
    __shared__ float ss[256], sc[256];
    ss[tid] = g_block[2 * tid + 0];
    sc[tid] = g_block[2 * tid + 1];
    __syncthreads();
    for (int o = 128; o > 0; o >>= 1) {
        if (tid < o) { ss[tid] += ss[tid + o]; sc[tid] += sc[tid + o]; }
        __syncthreads();
    }
    if (tid == 0) out[0] = ss[0] / sc[0];
}

extern "C" void kernel_launch(void* const* d_in, const int* in_sizes, int n_in,
                              void* d_out, int out_size) {
    const float* pc0 = (const float*)d_in[0];
    const float* pc1 = (const float*)d_in[1];
    (void)in_sizes; (void)n_in; (void)out_size;

    pack_k<<<(NPTS / 4) / 128, 128>>>(pc1);
    nn_k<<<G0 * G1, 128>>>(pc0);
    reduce_k<<<RB, 256>>>(pc0);
    final_k<<<1, 256>>>((float*)d_out);
}

// round 3
// speedup vs baseline: 1.4018x; 1.3353x over previous
#include <cuda_runtime.h>

// ---------------------------------------------------------------------------
// Grid-accelerated exact nearest neighbor (chamfer forward, masked mean).
// pc1 is counting-sorted into a 64^3 uniform grid over [-4,4]^3 (h=0.125).
// Each pc0 point expands Chebyshev shells until the ring lower bound proves
// the min (or proves the point is masked out, d>2).
// ---------------------------------------------------------------------------

#define NPTS 65536
#define GD   64
#define NC   (GD * GD * GD)          // 262144 cells
#define H    0.125f
#define INVH 8.0f
#define GOFF 4.0f
#define SB   256                     // search blocks
#define ST   256                     // search threads/block

// Scratch (no allocations allowed -> __device__ globals)
__device__ int    g_count[NC];
__device__ int    g_off[NC + 1];
__device__ int    g_cursor[NC];
__device__ int    g_bsum[256];
__device__ float4 g_pts[NPTS];       // sorted pc1: (x, y, z, ||b||^2)
__device__ float  g_block[SB * 2];   // per-block (sum, count)

__device__ __forceinline__ int cellc(float v) {
    int c = (int)floorf((v + GOFF) * INVH);
    return min(GD - 1, max(0, c));
}

// ---------------------------------------------------------------------------
__global__ void zero_k() {
    int i = blockIdx.x * blockDim.x + threadIdx.x;
    if (i < NC) g_count[i] = 0;
}

__global__ void count_k(const float* __restrict__ pc1) {
    int i = blockIdx.x * blockDim.x + threadIdx.x;
    float x = pc1[3 * i], y = pc1[3 * i + 1], z = pc1[3 * i + 2];
    int c = (cellc(z) * GD + cellc(y)) * GD + cellc(x);
    atomicAdd(&g_count[c], 1);
}

// --- 3-phase exclusive scan over NC cells (256 blocks x 256 thr x 4 cells) ---
__global__ void scan_a() {
    int t = threadIdx.x;
    int base = (blockIdx.x * 256 + t) * 4;
    int s = g_count[base] + g_count[base + 1] + g_count[base + 2] + g_count[base + 3];
    __shared__ int sh[256];
    sh[t] = s; __syncthreads();
    for (int o = 1; o < 256; o <<= 1) {
        int u = (t >= o) ? sh[t - o] : 0; __syncthreads();
        sh[t] += u; __syncthreads();
    }
    if (t == 255) g_bsum[blockIdx.x] = sh[255];
}

__global__ void scan_b() {
    int t = threadIdx.x;
    __shared__ int sh[256];
    int v = g_bsum[t];
    sh[t] = v; __syncthreads();
    for (int o = 1; o < 256; o <<= 1) {
        int u = (t >= o) ? sh[t - o] : 0; __syncthreads();
        sh[t] += u; __syncthreads();
    }
    g_bsum[t] = sh[t] - v;   // exclusive
}

__global__ void scan_c() {
    int t = threadIdx.x;
    int base = (blockIdx.x * 256 + t) * 4;
    int c0 = g_count[base], c1 = g_count[base + 1];
    int c2 = g_count[base + 2], c3 = g_count[base + 3];
    int s = c0 + c1 + c2 + c3;
    __shared__ int sh[256];
    sh[t] = s; __syncthreads();
    for (int o = 1; o < 256; o <<= 1) {
        int u = (t >= o) ? sh[t - o] : 0; __syncthreads();
        sh[t] += u; __syncthreads();
    }
    int o0 = sh[t] - s + g_bsum[blockIdx.x];
    int o1 = o0 + c0, o2 = o1 + c1, o3 = o2 + c2;
    g_off[base] = o0;     g_off[base + 1] = o1;
    g_off[base + 2] = o2; g_off[base + 3] = o3;
    g_cursor[base] = o0;     g_cursor[base + 1] = o1;
    g_cursor[base + 2] = o2; g_cursor[base + 3] = o3;
    if (blockIdx.x == 0 && t == 0) g_off[NC] = NPTS;
}

__global__ void scatter_k(const float* __restrict__ pc1) {
    int i = blockIdx.x * blockDim.x + threadIdx.x;
    float x = pc1[3 * i], y = pc1[3 * i + 1], z = pc1[3 * i + 2];
    int c = (cellc(z) * GD + cellc(y)) * GD + cellc(x);
    int idx = atomicAdd(&g_cursor[c], 1);
    float bsq = x * x + y * y + z * z;
    g_pts[idx] = make_float4(x, y, z, bsq);
}

// ---------------------------------------------------------------------------
// Search: one thread per pc0 point, expanding-shell exact NN.
// cur tracks min over candidates of t = ||b||^2 - 2 a.b  (same fma chain as
// the validated brute-force kernel); full d = cur + ||a||^2.
// ---------------------------------------------------------------------------
__global__ void __launch_bounds__(ST) search_k(const float* __restrict__ pc0) {
    int t = threadIdx.x;
    int i = blockIdx.x * ST + t;

    float ax = pc0[3 * i], ay = pc0[3 * i + 1], az = pc0[3 * i + 2];
    float nax = -2.f * ax, nay = -2.f * ay, naz = -2.f * az;
    float asq = fmaf(ax, ax, fmaf(ay, ay, az * az));
    int cx = cellc(ax), cy = cellc(ay), cz = cellc(az);

    float cur = 1e30f;

    auto scan_run = [&](int c0, int c1) {
        int s = g_off[c0], e = g_off[c1 + 1];
        for (int k = s; k < e; k++) {
            float4 p = g_pts[k];
            float d = fmaf(nax, p.x, fmaf(nay, p.y, fmaf(naz, p.z, p.w)));
            cur = fminf(cur, d);
        }
    };

    for (int r = 0; r <= 16; r++) {
        int z0 = max(cz - r, 0), z1 = min(cz + r, GD - 1);
        int y0 = max(cy - r, 0), y1 = min(cy + r, GD - 1);
        int xl = cx - r, xr = cx + r;
        int x0 = max(xl, 0), x1 = min(xr, GD - 1);
        for (int z = z0; z <= z1; z++) {
            bool zedge = (z == cz - r) || (z == cz + r);
            for (int y = y0; y <= y1; y++) {
                bool yedge = (y == cy - r) || (y == cy + r);
                int rowb = (z * GD + y) * GD;
                if (zedge || yedge) {
                    scan_run(rowb + x0, rowb + x1);     // full x-run (contiguous)
                } else {
                    if (xl >= 0)      scan_run(rowb + xl, rowb + xl);
                    if (xr <= GD - 1) scan_run(rowb + xr, rowb + xr);
                }
            }
        }
        float rh = r * H;
        float rh2 = rh * rh;
        // remaining (unscanned) points have full d >= rh2
        if (cur + asq <= rh2 || rh2 > 2.0f) break;
    }

    float d = cur + asq;
    float s = 0.f, c = 0.f;
    if (d <= 2.0f) { s = d; c = 1.f; }

    __shared__ float ss[ST], sc[ST];
    ss[t] = s; sc[t] = c;
    __syncthreads();
    for (int o = ST / 2; o > 0; o >>= 1) {
        if (t < o) { ss[t] += ss[t + o]; sc[t] += sc[t + o]; }
        __syncthreads();
    }
    if (t == 0) {
        g_block[2 * blockIdx.x + 0] = ss[0];
        g_block[2 * blockIdx.x + 1] = sc[0];
    }
}

// ---------------------------------------------------------------------------
__global__ void final_k(float* __restrict__ out) {
    int t = threadIdx.x;
    __shared__ float ss[256], sc[256];
    ss[t] = g_block[2 * t + 0];
    sc[t] = g_block[2 * t + 1];
    __syncthreads();
    for (int o = 128; o > 0; o >>= 1) {
        if (t < o) { ss[t] += ss[t + o]; sc[t] += sc[t + o]; }
        __syncthreads();
    }
    if (t == 0) out[0] = ss[0] / sc[0];
}

extern "C" void kernel_launch(void* const* d_in, const int* in_sizes, int n_in,
                              void* d_out, int out_size) {
    const float* pc0 = (const float*)d_in[0];
    const float* pc1 = (const float*)d_in[1];
    (void)in_sizes; (void)n_in; (void)out_size;

    zero_k   <<<NC / 256, 256>>>();
    count_k  <<<NPTS / 256, 256>>>(pc1);
    scan_a   <<<256, 256>>>();
    scan_b   <<<1, 256>>>();
    scan_c   <<<256, 256>>>();
    scatter_k<<<NPTS / 256, 256>>>(pc1);
    search_k <<<SB, ST>>>(pc0);
    final_k  <<<1, 256>>>((float*)d_out);
}

// round 5
// speedup vs baseline: 1.5105x; 1.0775x over previous
#include <cuda_runtime.h>

// ---------------------------------------------------------------------------
// Grid-accelerated exact nearest neighbor (chamfer forward, masked mean).
// BOTH clouds are counting-sorted into a 64^3 uniform grid over [-4,4]^3
// (h=0.125). Sorting pc0 makes warp lanes spatially coherent: uniform shell
// counts + coalesced g_off/g_pts gathers. Output is a global masked mean, so
// pc0 identity/order is irrelevant.
// ---------------------------------------------------------------------------

#define NPTS 65536
#define GD   64
#define NC   (GD * GD * GD)          // 262144 cells
#define H    0.125f
#define INVH 8.0f
#define GOFF 4.0f
#define SB   256                     // search blocks
#define ST   256                     // search threads/block

// Scratch (no allocations allowed -> __device__ globals)
__device__ int    g_count [NC];      // pc1 grid
__device__ int    g_off   [NC + 1];
__device__ int    g_cursor[NC];
__device__ int    g_bsum  [256];
__device__ int    g_count0 [NC];     // pc0 grid
__device__ int    g_off0   [NC + 1];
__device__ int    g_cursor0[NC];
__device__ int    g_bsum0  [256];
__device__ float4 g_pts [NPTS];      // sorted pc1: (x, y, z, ||b||^2)
__device__ float4 g_pts0[NPTS];      // sorted pc0: (x, y, z, ||a||^2)
__device__ float  g_block[SB * 2];   // per-block (sum, count)

__device__ __forceinline__ int cellc(float v) {
    int c = (int)floorf((v + GOFF) * INVH);
    return min(GD - 1, max(0, c));
}

// ---------------------------------------------------------------------------
__global__ void zero_k() {
    int i = blockIdx.x * blockDim.x + threadIdx.x;
    if (i < NC) { g_count[i] = 0; g_count0[i] = 0; }
}

__global__ void count_k(const float* __restrict__ pc1,
                        const float* __restrict__ pc0) {
    int i = blockIdx.x * blockDim.x + threadIdx.x;
    {
        float x = pc1[3 * i], y = pc1[3 * i + 1], z = pc1[3 * i + 2];
        atomicAdd(&g_count[(cellc(z) * GD + cellc(y)) * GD + cellc(x)], 1);
    }
    {
        float x = pc0[3 * i], y = pc0[3 * i + 1], z = pc0[3 * i + 2];
        atomicAdd(&g_count0[(cellc(z) * GD + cellc(y)) * GD + cellc(x)], 1);
    }
}

// --- 3-phase exclusive scan over NC cells (256 blocks x 256 thr x 4 cells) ---
__global__ void scan_a(int which) {
    int* cnt  = which ? g_count0 : g_count;
    int* bsum = which ? g_bsum0  : g_bsum;
    int t = threadIdx.x;
    int base = (blockIdx.x * 256 + t) * 4;
    int s = cnt[base] + cnt[base + 1] + cnt[base + 2] + cnt[base + 3];
    __shared__ int sh[256];
    sh[t] = s; __syncthreads();
    for (int o = 1; o < 256; o <<= 1) {
        int u = (t >= o) ? sh[t - o] : 0; __syncthreads();
        sh[t] += u; __syncthreads();
    }
    if (t == 255) bsum[blockIdx.x] = sh[255];
}

__global__ void scan_b(int which) {
    int* bsum = which ? g_bsum0 : g_bsum;
    int t = threadIdx.x;
    __shared__ int sh[256];
    int v = bsum[t];
    sh[t] = v; __syncthreads();
    for (int o = 1; o < 256; o <<= 1) {
        int u = (t >= o) ? sh[t - o] : 0; __syncthreads();
        sh[t] += u; __syncthreads();
    }
    bsum[t] = sh[t] - v;   // exclusive
}

__global__ void scan_c(int which) {
    int* cnt  = which ? g_count0  : g_count;
    int* off  = which ? g_off0    : g_off;
    int* cur  = which ? g_cursor0 : g_cursor;
    int* bsum = which ? g_bsum0   : g_bsum;
    int t = threadIdx.x;
    int base = (blockIdx.x * 256 + t) * 4;
    int c0 = cnt[base], c1 = cnt[base + 1];
    int c2 = cnt[base + 2], c3 = cnt[base + 3];
    int s = c0 + c1 + c2 + c3;
    __shared__ int sh[256];
    sh[t] = s; __syncthreads();
    for (int o = 1; o < 256; o <<= 1) {
        int u = (t >= o) ? sh[t - o] : 0; __syncthreads();
        sh[t] += u; __syncthreads();
    }
    int o0 = sh[t] - s + bsum[blockIdx.x];
    int o1 = o0 + c0, o2 = o1 + c1, o3 = o2 + c2;
    off[base] = o0;     off[base + 1] = o1;
    off[base + 2] = o2; off[base + 3] = o3;
    cur[base] = o0;     cur[base + 1] = o1;
    cur[base + 2] = o2; cur[base + 3] = o3;
    if (blockIdx.x == 0 && t == 0) off[NC] = NPTS;
}

__global__ void scatter_k(const float* __restrict__ pc1,
                          const float* __restrict__ pc0) {
    int i = blockIdx.x * blockDim.x + threadIdx.x;
    {
        float x = pc1[3 * i], y = pc1[3 * i + 1], z = pc1[3 * i + 2];
        int c = (cellc(z) * GD + cellc(y)) * GD + cellc(x);
        int idx = atomicAdd(&g_cursor[c], 1);
        g_pts[idx] = make_float4(x, y, z, x * x + y * y + z * z);
    }
    {
        float x = pc0[3 * i], y = pc0[3 * i + 1], z = pc0[3 * i + 2];
        int c = (cellc(z) * GD + cellc(y)) * GD + cellc(x);
        int idx = atomicAdd(&g_cursor0[c], 1);
        g_pts0[idx] = make_float4(x, y, z, fmaf(x, x, fmaf(y, y, z * z)));
    }
}

// ---------------------------------------------------------------------------
// Search: one thread per SORTED pc0 point, expanding-shell exact NN.
// cur tracks min over candidates of t = ||b||^2 - 2 a.b  (same fma chain as
// the validated brute-force kernel); full d = cur + ||a||^2.
// ---------------------------------------------------------------------------
__global__ void __launch_bounds__(ST) search_k() {
    int t = threadIdx.x;
    int i = blockIdx.x * ST + t;

    float4 a = g_pts0[i];
    float ax = a.x, ay = a.y, az = a.z, asq = a.w;
    float nax = -2.f * ax, nay = -2.f * ay, naz = -2.f * az;
    int cx = cellc(ax), cy = cellc(ay), cz = cellc(az);

    float cur = 1e30f;

    auto scan_run = [&](int c0, int c1) {
        int s = g_off[c0], e = g_off[c1 + 1];
        for (int k = s; k < e; k++) {
            float4 p = g_pts[k];
            float d = fmaf(nax, p.x, fmaf(nay, p.y, fmaf(naz, p.z, p.w)));
            cur = fminf(cur, d);
        }
    };

    for (int r = 0; r <= 16; r++) {
        int z0 = max(cz - r, 0), z1 = min(cz + r, GD - 1);
        int y0 = max(cy - r, 0), y1 = min(cy + r, GD - 1);
        int xl = cx - r, xr = cx + r;
        int x0 = max(xl, 0), x1 = min(xr, GD - 1);
        for (int z = z0; z <= z1; z++) {
            bool zedge = (z == cz - r) || (z == cz + r);
            for (int y = y0; y <= y1; y++) {
                bool yedge = (y == cy - r) || (y == cy + r);
                int rowb = (z * GD + y) * GD;
                if (zedge || yedge) {
                    scan_run(rowb + x0, rowb + x1);     // full x-run (contiguous)
                } else {
                    if (xl >= 0)      scan_run(rowb + xl, rowb + xl);
                    if (xr <= GD - 1) scan_run(rowb + xr, rowb + xr);
                }
            }
        }
        float rh = r * H;
        float rh2 = rh * rh;
        // remaining (unscanned) points have full d >= rh2
        if (cur + asq <= rh2 || rh2 > 2.0f) break;
    }

    float d = cur + asq;
    float s = 0.f, c = 0.f;
    if (d <= 2.0f) { s = d; c = 1.f; }

    __shared__ float ss[ST], sc[ST];
    ss[t] = s; sc[t] = c;
    __syncthreads();
    for (int o = ST / 2; o > 0; o >>= 1) {
        if (t < o) { ss[t] += ss[t + o]; sc[t] += sc[t + o]; }
        __syncthreads();
    }
    if (t == 0) {
        g_block[2 * blockIdx.x + 0] = ss[0];
        g_block[2 * blockIdx.x + 1] = sc[0];
    }
}

// ---------------------------------------------------------------------------
__global__ void final_k(float* __restrict__ out) {
    int t = threadIdx.x;
    __shared__ float ss[256], sc[256];
    ss[t] = g_block[2 * t + 0];
    sc[t] = g_block[2 * t + 1];
    __syncthreads();
    for (int o = 128; o > 0; o >>= 1) {
        if (t < o) { ss[t] += ss[t + o]; sc[t] += sc[t + o]; }
        __syncthreads();
    }
    if (t == 0) out[0] = ss[0] / sc[0];
}

extern "C" void kernel_launch(void* const* d_in, const int* in_sizes, int n_in,
                              void* d_out, int out_size) {
    const float* pc0 = (const float*)d_in[0];
    const float* pc1 = (const float*)d_in[1];
    (void)in_sizes; (void)n_in; (void)out_size;

    zero_k   <<<NC / 256, 256>>>();
    count_k  <<<NPTS / 256, 256>>>(pc1, pc0);
    scan_a   <<<256, 256>>>(0);
    scan_b   <<<1, 256>>>(0);
    scan_c   <<<256, 256>>>(0);
    scan_a   <<<256, 256>>>(1);
    scan_b   <<<1, 256>>>(1);
    scan_c   <<<256, 256>>>(1);
    scatter_k<<<NPTS / 256, 256>>>(pc1, pc0);
    search_k <<<SB, ST>>>();
    final_k  <<<1, 256>>>((float*)d_out);
}

// round 6
// speedup vs baseline: 3.9942x; 2.6442x over previous
#include <cuda_runtime.h>

// ---------------------------------------------------------------------------
// Grid-accelerated exact NN (chamfer forward, masked mean) with occupancy
// bitmasks so empty-space shell traversal costs ~1 load per row/plane.
// Both clouds counting-sorted into a 64^3 grid over [-4,4]^3 (h=0.125).
// ---------------------------------------------------------------------------

#define NPTS 65536
#define GD   64
#define NC   (GD * GD * GD)
#define H    0.125f
#define INVH 8.0f
#define GOFF 4.0f
#define SB   256
#define ST   256

typedef unsigned long long u64;

// Scratch (no allocations -> __device__ globals)
__device__ int    g_count [NC];      // pc1 grid
__device__ int    g_off   [NC + 1];
__device__ int    g_cursor[NC];
__device__ int    g_count0 [NC];     // pc0 grid
__device__ int    g_off0   [NC + 1];
__device__ int    g_cursor0[NC];
__device__ int    g_bsum  [2][256];
__device__ u64    g_occ [GD * GD];   // per (z,y) row: occupied x bits (pc1)
__device__ u64    g_occX[GD * GD];   // per (z,x) column: occupied y bits (pc1)
__device__ u64    g_occP[GD];        // per z plane: nonempty-row y bits
__device__ float4 g_pts [NPTS];      // sorted pc1: (x,y,z,||b||^2)
__device__ float4 g_pts0[NPTS];      // sorted pc0: (x,y,z,||a||^2)
__device__ float  g_block[SB * 2];

__device__ __forceinline__ int cellc(float v) {
    int c = (int)floorf((v + GOFF) * INVH);
    return min(GD - 1, max(0, c));
}
__device__ __forceinline__ u64 bitrange(int lo, int hi) {  // bits lo..hi, 0<=lo<=hi<=63
    return (~0ull << lo) & (~0ull >> (63 - hi));
}

// ---------------------------------------------------------------------------
__global__ void zero_k() {
    int i = blockIdx.x * blockDim.x + threadIdx.x;
    if (i < NC) { g_count[i] = 0; g_count0[i] = 0; }
    if (i < GD * GD) { g_occ[i] = 0; g_occX[i] = 0; }
}

__global__ void count_k(const float* __restrict__ pc1,
                        const float* __restrict__ pc0) {
    int i = blockIdx.x * blockDim.x + threadIdx.x;
    {
        float x = pc1[3 * i], y = pc1[3 * i + 1], z = pc1[3 * i + 2];
        int cx = cellc(x), cy = cellc(y), cz = cellc(z);
        atomicAdd(&g_count[(cz * GD + cy) * GD + cx], 1);
        atomicOr(&g_occ [cz * GD + cy], 1ull << cx);
        atomicOr(&g_occX[cz * GD + cx], 1ull << cy);
    }
    {
        float x = pc0[3 * i], y = pc0[3 * i + 1], z = pc0[3 * i + 2];
        atomicAdd(&g_count0[(cellc(z) * GD + cellc(y)) * GD + cellc(x)], 1);
    }
}

__global__ void occp_k() {
    int z = threadIdx.x;
    u64 w = 0;
    for (int y = 0; y < GD; y++)
        if (g_occ[z * GD + y]) w |= 1ull << y;
    g_occP[z] = w;
}

// --- 3-phase exclusive scan, both grids in one launch (blockIdx.y / x) ---
__global__ void scan_a() {
    int which = blockIdx.y;
    int* cnt = which ? g_count0 : g_count;
    int t = threadIdx.x;
    int base = (blockIdx.x * 256 + t) * 4;
    int s = cnt[base] + cnt[base + 1] + cnt[base + 2] + cnt[base + 3];
    __shared__ int sh[256];
    sh[t] = s; __syncthreads();
    for (int o = 1; o < 256; o <<= 1) {
        int u = (t >= o) ? sh[t - o] : 0; __syncthreads();
        sh[t] += u; __syncthreads();
    }
    if (t == 255) g_bsum[which][blockIdx.x] = sh[255];
}

__global__ void scan_b() {
    int which = blockIdx.x;
    int t = threadIdx.x;
    __shared__ int sh[256];
    int v = g_bsum[which][t];
    sh[t] = v; __syncthreads();
    for (int o = 1; o < 256; o <<= 1) {
        int u = (t >= o) ? sh[t - o] : 0; __syncthreads();
        sh[t] += u; __syncthreads();
    }
    g_bsum[which][t] = sh[t] - v;
}

__global__ void scan_c() {
    int which = blockIdx.y;
    int* cnt = which ? g_count0  : g_count;
    int* off = which ? g_off0    : g_off;
    int* cur = which ? g_cursor0 : g_cursor;
    int t = threadIdx.x;
    int base = (blockIdx.x * 256 + t) * 4;
    int c0 = cnt[base], c1 = cnt[base + 1];
    int c2 = cnt[base + 2], c3 = cnt[base + 3];
    int s = c0 + c1 + c2 + c3;
    __shared__ int sh[256];
    sh[t] = s; __syncthreads();
    for (int o = 1; o < 256; o <<= 1) {
        int u = (t >= o) ? sh[t - o] : 0; __syncthreads();
        sh[t] += u; __syncthreads();
    }
    int o0 = sh[t] - s + g_bsum[which][blockIdx.x];
    int o1 = o0 + c0, o2 = o1 + c1, o3 = o2 + c2;
    off[base] = o0;     off[base + 1] = o1;
    off[base + 2] = o2; off[base + 3] = o3;
    cur[base] = o0;     cur[base + 1] = o1;
    cur[base + 2] = o2; cur[base + 3] = o3;
    if (blockIdx.x == 0 && t == 0) off[NC] = NPTS;
}

__global__ void scatter_k(const float* __restrict__ pc1,
                          const float* __restrict__ pc0) {
    int i = blockIdx.x * blockDim.x + threadIdx.x;
    {
        float x = pc1[3 * i], y = pc1[3 * i + 1], z = pc1[3 * i + 2];
        int c = (cellc(z) * GD + cellc(y)) * GD + cellc(x);
        int idx = atomicAdd(&g_cursor[c], 1);
        g_pts[idx] = make_float4(x, y, z, x * x + y * y + z * z);
    }
    {
        float x = pc0[3 * i], y = pc0[3 * i + 1], z = pc0[3 * i + 2];
        int c = (cellc(z) * GD + cellc(y)) * GD + cellc(x);
        int idx = atomicAdd(&g_cursor0[c], 1);
        g_pts0[idx] = make_float4(x, y, z, fmaf(x, x, fmaf(y, y, z * z)));
    }
}

// ---------------------------------------------------------------------------
// Search: one thread per sorted pc0 point; expanding Chebyshev shells with
// bitmask-gated cell scanning. cur = min over candidates of ||b||^2 - 2 a.b;
// full d = cur + ||a||^2 (same fma chain as the validated brute-force).
// ---------------------------------------------------------------------------
__global__ void __launch_bounds__(ST) search_k() {
    __shared__ u64 s_occ[GD * GD];     // 32 KB
    int t = threadIdx.x;
#pragma unroll
    for (int k = t; k < GD * GD; k += ST) s_occ[k] = g_occ[k];
    __syncthreads();

    int i = blockIdx.x * ST + t;
    float4 a = g_pts0[i];
    float nax = -2.f * a.x, nay = -2.f * a.y, naz = -2.f * a.z;
    float asq = a.w;
    int cx = cellc(a.x), cy = cellc(a.y), cz = cellc(a.z);

    float cur = 1e30f;

    auto scan_run = [&](int c0, int c1) {
        int s = __ldg(&g_off[c0]);
        int e = __ldg(&g_off[c1 + 1]);
        for (int k = s; k < e; k++) {
            float4 p = __ldg(&g_pts[k]);
            cur = fminf(cur, fmaf(nax, p.x, fmaf(nay, p.y, fmaf(naz, p.z, p.w))));
        }
    };

    for (int r = 0; r <= 12; r++) {
        int z0 = max(cz - r, 0), z1 = min(cz + r, GD - 1);
        int y0 = max(cy - r, 0), y1 = min(cy + r, GD - 1);
        int xl = cx - r, xr = cx + r;
        int x0 = max(xl, 0), x1 = min(xr, GD - 1);
        u64 xm = bitrange(x0, x1);

        for (int z = z0; z <= z1; z++) {
            int zb = z * GD;
            bool zedge = (z == cz - r) || (z == cz + r);
            if (zedge) {
                // full plane: iterate nonempty rows within y range
                u64 wp = __ldg(&g_occP[z]) & bitrange(y0, y1);
                while (wp) {
                    int y = __ffsll((long long)wp) - 1; wp &= wp - 1;
                    u64 w = s_occ[zb + y] & xm;
                    if (w) {
                        int lo = __ffsll((long long)w) - 1;
                        int hi = 63 - __clzll(w);
                        scan_run((zb + y) * GD + lo, (zb + y) * GD + hi);
                    }
                }
            } else {
                // y-edge rows: full x runs
                int yl = cy - r, yr2 = cy + r;
                if (yl >= 0) {
                    u64 w = s_occ[zb + yl] & xm;
                    if (w) {
                        int lo = __ffsll((long long)w) - 1;
                        int hi = 63 - __clzll(w);
                        scan_run((zb + yl) * GD + lo, (zb + yl) * GD + hi);
                    }
                }
                if (yr2 <= GD - 1) {
                    u64 w = s_occ[zb + yr2] & xm;
                    if (w) {
                        int lo = __ffsll((long long)w) - 1;
                        int hi = 63 - __clzll(w);
                        scan_run((zb + yr2) * GD + lo, (zb + yr2) * GD + hi);
                    }
                }
                // interior rows: only columns xl and xr (bitmask over y)
                int yi0 = max(yl + 1, 0), yi1 = min(yr2 - 1, GD - 1);
                if (yi0 <= yi1) {
                    u64 ym = bitrange(yi0, yi1);
                    if (xl >= 0) {
                        u64 wc = __ldg(&g_occX[zb + xl]) & ym;
                        while (wc) {
                            int y = __ffsll((long long)wc) - 1; wc &= wc - 1;
                            int c = (zb + y) * GD + xl;
                            scan_run(c, c);
                        }
                    }
                    if (xr <= GD - 1) {
                        u64 wc = __ldg(&g_occX[zb + xr]) & ym;
                        while (wc) {
                            int y = __ffsll((long long)wc) - 1; wc &= wc - 1;
                            int c = (zb + y) * GD + xr;
                            scan_run(c, c);
                        }
                    }
                }
            }
        }
        float rh = r * H;
        float rh2 = rh * rh;
        if (cur + asq <= rh2 || rh2 > 2.0f) break;   // unscanned have d >= rh2
    }

    float d = cur + asq;
    float s = 0.f, c = 0.f;
    if (d <= 2.0f) { s = d; c = 1.f; }

    __shared__ float ss[ST], sc[ST];
    ss[t] = s; sc[t] = c;
    __syncthreads();
    for (int o = ST / 2; o > 0; o >>= 1) {
        if (t < o) { ss[t] += ss[t + o]; sc[t] += sc[t + o]; }
        __syncthreads();
    }
    if (t == 0) {
        g_block[2 * blockIdx.x + 0] = ss[0];
        g_block[2 * blockIdx.x + 1] = sc[0];
    }
}

// ---------------------------------------------------------------------------
__global__ void final_k(float* __restrict__ out) {
    int t = threadIdx.x;
    __shared__ float ss[256], sc[256];
    ss[t] = g_block[2 * t + 0];
    sc[t] = g_block[2 * t + 1];
    __syncthreads();
    for (int o = 128; o > 0; o >>= 1) {
        if (t < o) { ss[t] += ss[t + o]; sc[t] += sc[t + o]; }
        __syncthreads();
    }
    if (t == 0) out[0] = ss[0] / sc[0];
}

extern "C" void kernel_launch(void* const* d_in, const int* in_sizes, int n_in,
                              void* d_out, int out_size) {
    const float* pc0 = (const float*)d_in[0];
    const float* pc1 = (const float*)d_in[1];
    (void)in_sizes; (void)n_in; (void)out_size;

    zero_k   <<<NC / 256, 256>>>();
    count_k  <<<NPTS / 256, 256>>>(pc1, pc0);
    occp_k   <<<1, GD>>>();
    scan_a   <<<dim3(256, 2), 256>>>();
    scan_b   <<<2, 256>>>();
    scan_c   <<<dim3(256, 2), 256>>>();
    scatter_k<<<NPTS / 256, 256>>>(pc1, pc0);
    search_k <<<SB, ST>>>();
    final_k  <<<1, 256>>>((float*)d_out);
}

// round 8
// speedup vs baseline: 4.0544x; 1.0151x over previous
#include <cuda_runtime.h>

// ---------------------------------------------------------------------------
// Grid-accelerated exact NN (chamfer forward, masked mean) with occupancy
// bitmasks. Both clouds counting-sorted into 64^3 grid over [-4,4]^3.
// Search: 2 lanes per pc0 point (z-plane parity split); pair combine uses a
// PAIR-LOCAL shuffle mask (full-warp mask deadlocked when pairs exited at
// different shell radii).
// ---------------------------------------------------------------------------

#define NPTS 65536
#define GD   64
#define NC   (GD * GD * GD)
#define H    0.125f
#define INVH 8.0f
#define GOFF 4.0f
#define ST   128
#define SB   (2 * NPTS / ST)         // 1024 blocks, 2 threads per point

typedef unsigned long long u64;

// Scratch (no allocations -> __device__ globals)
__device__ int    g_count [NC];      // pc1 grid
__device__ int    g_off   [NC + 1];
__device__ int    g_cursor[NC];
__device__ int    g_count0 [NC];     // pc0 grid
__device__ int    g_off0   [NC + 1];
__device__ int    g_cursor0[NC];
__device__ int    g_bsum  [2][256];
__device__ u64    g_occ [GD * GD];   // per (z,y) row: occupied x bits (pc1)
__device__ u64    g_occX[GD * GD];   // per (z,x) column: occupied y bits (pc1)
__device__ u64    g_occP[GD];        // per z plane: nonempty-row y bits
__device__ float4 g_pts [NPTS];      // sorted pc1: (x,y,z,||b||^2)
__device__ float4 g_pts0[NPTS];      // sorted pc0: (x,y,z,||a||^2)
__device__ float  g_block[SB * 2];

__device__ __forceinline__ int cellc(float v) {
    int c = (int)floorf((v + GOFF) * INVH);
    return min(GD - 1, max(0, c));
}
__device__ __forceinline__ u64 bitrange(int lo, int hi) {
    return (~0ull << lo) & (~0ull >> (63 - hi));
}

// ---------------------------------------------------------------------------
__global__ void zero_k() {
    int i = blockIdx.x * blockDim.x + threadIdx.x;
    if (i < NC) { g_count[i] = 0; g_count0[i] = 0; }
    if (i < GD * GD) { g_occ[i] = 0; g_occX[i] = 0; }
    if (i < GD) g_occP[i] = 0;
}

__global__ void count_k(const float* __restrict__ pc1,
                        const float* __restrict__ pc0) {
    int i = blockIdx.x * blockDim.x + threadIdx.x;
    {
        float x = pc1[3 * i], y = pc1[3 * i + 1], z = pc1[3 * i + 2];
        int cx = cellc(x), cy = cellc(y), cz = cellc(z);
        atomicAdd(&g_count[(cz * GD + cy) * GD + cx], 1);
        atomicOr(&g_occ [cz * GD + cy], 1ull << cx);
        atomicOr(&g_occX[cz * GD + cx], 1ull << cy);
    }
    {
        float x = pc0[3 * i], y = pc0[3 * i + 1], z = pc0[3 * i + 2];
        atomicAdd(&g_count0[(cellc(z) * GD + cellc(y)) * GD + cellc(x)], 1);
    }
}

// --- 3-phase exclusive scan, both grids via grid.y / grid.x ---
__global__ void scan_a() {
    int which = blockIdx.y;
    int* cnt = which ? g_count0 : g_count;
    int t = threadIdx.x;
    int base = (blockIdx.x * 256 + t) * 4;
    int s = cnt[base] + cnt[base + 1] + cnt[base + 2] + cnt[base + 3];
    __shared__ int sh[256];
    sh[t] = s; __syncthreads();
    for (int o = 1; o < 256; o <<= 1) {
        int u = (t >= o) ? sh[t - o] : 0; __syncthreads();
        sh[t] += u; __syncthreads();
    }
    if (t == 255) g_bsum[which][blockIdx.x] = sh[255];
}

// blocks 0,1: block-sum scans; block 2: build g_occP from g_occ
__global__ void scan_b() {
    int t = threadIdx.x;
    if (blockIdx.x == 2) {
        int z = t >> 2, q = t & 3;
        u64 w = 0;
        for (int y = q * 16; y < q * 16 + 16; y++)
            if (g_occ[z * GD + y]) w |= 1ull << y;
        if (w) atomicOr(&g_occP[z], w);
        return;
    }
    int which = blockIdx.x;
    __shared__ int sh[256];
    int v = g_bsum[which][t];
    sh[t] = v; __syncthreads();
    for (int o = 1; o < 256; o <<= 1) {
        int u = (t >= o) ? sh[t - o] : 0; __syncthreads();
        sh[t] += u; __syncthreads();
    }
    g_bsum[which][t] = sh[t] - v;
}

__global__ void scan_c() {
    int which = blockIdx.y;
    int* cnt = which ? g_count0  : g_count;
    int* off = which ? g_off0    : g_off;
    int* cur = which ? g_cursor0 : g_cursor;
    int t = threadIdx.x;
    int base = (blockIdx.x * 256 + t) * 4;
    int c0 = cnt[base], c1 = cnt[base + 1];
    int c2 = cnt[base + 2], c3 = cnt[base + 3];
    int s = c0 + c1 + c2 + c3;
    __shared__ int sh[256];
    sh[t] = s; __syncthreads();
    for (int o = 1; o < 256; o <<= 1) {
        int u = (t >= o) ? sh[t - o] : 0; __syncthreads();
        sh[t] += u; __syncthreads();
    }
    int o0 = sh[t] - s + g_bsum[which][blockIdx.x];
    int o1 = o0 + c0, o2 = o1 + c1, o3 = o2 + c2;
    off[base] = o0;     off[base + 1] = o1;
    off[base + 2] = o2; off[base + 3] = o3;
    cur[base] = o0;     cur[base + 1] = o1;
    cur[base + 2] = o2; cur[base + 3] = o3;
    if (blockIdx.x == 0 && t == 0) off[NC] = NPTS;
}

__global__ void scatter_k(const float* __restrict__ pc1,
                          const float* __restrict__ pc0) {
    int i = blockIdx.x * blockDim.x + threadIdx.x;
    {
        float x = pc1[3 * i], y = pc1[3 * i + 1], z = pc1[3 * i + 2];
        int c = (cellc(z) * GD + cellc(y)) * GD + cellc(x);
        int idx = atomicAdd(&g_cursor[c], 1);
        g_pts[idx] = make_float4(x, y, z, x * x + y * y + z * z);
    }
    {
        float x = pc0[3 * i], y = pc0[3 * i + 1], z = pc0[3 * i + 2];
        int c = (cellc(z) * GD + cellc(y)) * GD + cellc(x);
        int idx = atomicAdd(&g_cursor0[c], 1);
        g_pts0[idx] = make_float4(x, y, z, fmaf(x, x, fmaf(y, y, z * z)));
    }
}

// ---------------------------------------------------------------------------
// Search: TWO adjacent lanes per sorted pc0 point, splitting shell z-planes
// by global z parity; per-shell combine via shfl_xor with PAIR-LOCAL mask
// (both lanes of a pair are always converged: same point, same loop bounds,
// shared break decision). 4 persistent min accumulators for MLP.
// ---------------------------------------------------------------------------
__global__ void __launch_bounds__(ST) search_k() {
    int t = threadIdx.x;
    int gid = blockIdx.x * ST + t;
    int i = gid >> 1;              // point index
    int par = gid & 1;             // z-plane parity handled by this lane
    unsigned pm = 3u << ((t & 31) & ~1);   // pair-local shuffle mask

    float4 a = __ldg(&g_pts0[i]);
    float nax = -2.f * a.x, nay = -2.f * a.y, naz = -2.f * a.z;
    float asq = a.w;
    int cx = cellc(a.x), cy = cellc(a.y), cz = cellc(a.z);

    float c0a = 1e30f, c1a = 1e30f, c2a = 1e30f, c3a = 1e30f;

    auto scan_run = [&](int cc0, int cc1) {
        int s = __ldg(&g_off[cc0]);
        int e = __ldg(&g_off[cc1 + 1]);
        int k = s;
        for (; k + 4 <= e; k += 4) {
            float4 p0 = __ldg(&g_pts[k]);
            float4 p1 = __ldg(&g_pts[k + 1]);
            float4 p2 = __ldg(&g_pts[k + 2]);
            float4 p3 = __ldg(&g_pts[k + 3]);
            c0a = fminf(c0a, fmaf(nax, p0.x, fmaf(nay, p0.y, fmaf(naz, p0.z, p0.w))));
            c1a = fminf(c1a, fmaf(nax, p1.x, fmaf(nay, p1.y, fmaf(naz, p1.z, p1.w))));
            c2a = fminf(c2a, fmaf(nax, p2.x, fmaf(nay, p2.y, fmaf(naz, p2.z, p2.w))));
            c3a = fminf(c3a, fmaf(nax, p3.x, fmaf(nay, p3.y, fmaf(naz, p3.z, p3.w))));
        }
        for (; k < e; k++) {
            float4 p = __ldg(&g_pts[k]);
            c0a = fminf(c0a, fmaf(nax, p.x, fmaf(nay, p.y, fmaf(naz, p.z, p.w))));
        }
    };

    float m = 1e30f;
    for (int r = 0; r <= 12; r++) {
        int z0 = max(cz - r, 0), z1 = min(cz + r, GD - 1);
        int y0 = max(cy - r, 0), y1 = min(cy + r, GD - 1);
        int xl = cx - r, xr = cx + r;
        int x0 = max(xl, 0), x1 = min(xr, GD - 1);
        u64 xm = bitrange(x0, x1);

        for (int z = z0; z <= z1; z++) {
            if ((z & 1) != par) continue;          // parity split
            int zb = z * GD;
            bool zedge = (z == cz - r) || (z == cz + r);
            if (zedge) {
                u64 wp = __ldg(&g_occP[z]) & bitrange(y0, y1);
                while (wp) {
                    int y = __ffsll((long long)wp) - 1; wp &= wp - 1;
                    u64 w = __ldg(&g_occ[zb + y]) & xm;
                    if (w) {
                        int lo = __ffsll((long long)w) - 1;
                        int hi = 63 - __clzll(w);
                        scan_run((zb + y) * GD + lo, (zb + y) * GD + hi);
                    }
                }
            } else {
                int yl = cy - r, yr2 = cy + r;
                if (yl >= 0) {
                    u64 w = __ldg(&g_occ[zb + yl]) & xm;
                    if (w) {
                        int lo = __ffsll((long long)w) - 1;
                        int hi = 63 - __clzll(w);
                        scan_run((zb + yl) * GD + lo, (zb + yl) * GD + hi);
                    }
                }
                if (yr2 <= GD - 1) {
                    u64 w = __ldg(&g_occ[zb + yr2]) & xm;
                    if (w) {
                        int lo = __ffsll((long long)w) - 1;
                        int hi = 63 - __clzll(w);
                        scan_run((zb + yr2) * GD + lo, (zb + yr2) * GD + hi);
                    }
                }
                int yi0 = max(yl + 1, 0), yi1 = min(yr2 - 1, GD - 1);
                if (yi0 <= yi1) {
                    u64 ym = bitrange(yi0, yi1);
                    if (xl >= 0) {
                        u64 wc = __ldg(&g_occX[zb + xl]) & ym;
                        while (wc) {
                            int y = __ffsll((long long)wc) - 1; wc &= wc - 1;
                            int c = (zb + y) * GD + xl;
                            scan_run(c, c);
                        }
                    }
                    if (xr <= GD - 1) {
                        u64 wc = __ldg(&g_occX[zb + xr]) & ym;
                        while (wc) {
                            int y = __ffsll((long long)wc) - 1; wc &= wc - 1;
                            int c = (zb + y) * GD + xr;
                            scan_run(c, c);
                        }
                    }
                }
            }
        }
        // combine across the lane pair (pair-local mask; both lanes converged)
        float ml = fminf(fminf(c0a, c1a), fminf(c2a, c3a));
        m = fminf(ml, __shfl_xor_sync(pm, ml, 1));
        float rh = r * H;
        float rh2 = rh * rh;
        if (m + asq <= rh2 || rh2 > 2.0f) break;   // unscanned have d >= rh2
    }

    float d = m + asq;
    float s = 0.f, c = 0.f;
    if (par == 0 && d <= 2.0f) { s = d; c = 1.f; }  // one lane per point counts

    __shared__ float ss[ST], sc[ST];
    ss[t] = s; sc[t] = c;
    __syncthreads();
    for (int o = ST / 2; o > 0; o >>= 1) {
        if (t < o) { ss[t] += ss[t + o]; sc[t] += sc[t + o]; }
        __syncthreads();
    }
    if (t == 0) {
        g_block[2 * blockIdx.x + 0] = ss[0];
        g_block[2 * blockIdx.x + 1] = sc[0];
    }
}

// ---------------------------------------------------------------------------
// Final: reduce SB=1024 block partials with 256 threads (4 each)
__global__ void final_k(float* __restrict__ out) {
    int t = threadIdx.x;
    float s = 0.f, c = 0.f;
#pragma unroll
    for (int k = 0; k < SB / 256; k++) {
        s += g_block[2 * (t + k * 256) + 0];
        c += g_block[2 * (t + k * 256) + 1];
    }
    __shared__ float ss[256], sc[256];
    ss[t] = s; sc[t] = c;
    __syncthreads();
    for (int o = 128; o > 0; o >>= 1) {
        if (t < o) { ss[t] += ss[t + o]; sc[t] += sc[t + o]; }
        __syncthreads();
    }
    if (t == 0) out[0] = ss[0] / sc[0];
}

extern "C" void kernel_launch(void* const* d_in, const int* in_sizes, int n_in,
                              void* d_out, int out_size) {
    const float* pc0 = (const float*)d_in[0];
    const float* pc1 = (const float*)d_in[1];
    (void)in_sizes; (void)n_in; (void)out_size;

    zero_k   <<<NC / 256, 256>>>();
    count_k  <<<NPTS / 256, 256>>>(pc1, pc0);
    scan_a   <<<dim3(256, 2), 256>>>();
    scan_b   <<<3, 256>>>();
    scan_c   <<<dim3(256, 2), 256>>>();
    scatter_k<<<NPTS / 256, 256>>>(pc1, pc0);
    search_k <<<SB, ST>>>();
    final_k  <<<1, 256>>>((float*)d_out);
}

// round 9
// speedup vs baseline: 4.2453x; 1.0471x over previous
#include <cuda_runtime.h>

// ---------------------------------------------------------------------------
// Grid-accelerated exact NN (chamfer forward, masked mean) with occupancy
// bitmasks. Both clouds counting-sorted into 64^3 grid over [-4,4]^3.
// Search: 8 lanes cooperate per pc0 point — uniform shell traversal
// (broadcast mask/offset loads) + 8-wide coalesced candidate scanning,
// group-local shuffle reduction per shell.
// ---------------------------------------------------------------------------

#define NPTS 65536
#define GD   64
#define NC   (GD * GD * GD)
#define H    0.125f
#define INVH 8.0f
#define GOFF 4.0f
#define ST   128
#define W    8                       // lanes per point
#define SB   (NPTS * W / ST)         // 4096 blocks

typedef unsigned long long u64;

// Scratch (no allocations -> __device__ globals)
__device__ int    g_count [NC];      // pc1 grid
__device__ int    g_off   [NC + 1];
__device__ int    g_cursor[NC];
__device__ int    g_count0 [NC];     // pc0 grid
__device__ int    g_off0   [NC + 1];
__device__ int    g_cursor0[NC];
__device__ int    g_bsum  [2][256];
__device__ u64    g_occ [GD * GD];   // per (z,y) row: occupied x bits (pc1)
__device__ u64    g_occX[GD * GD];   // per (z,x) column: occupied y bits (pc1)
__device__ u64    g_occP[GD];        // per z plane: nonempty-row y bits
__device__ float4 g_pts [NPTS];      // sorted pc1: (x,y,z,||b||^2)
__device__ float4 g_pts0[NPTS];      // sorted pc0: (x,y,z,||a||^2)
__device__ float  g_block[SB * 2];

__device__ __forceinline__ int cellc(float v) {
    int c = (int)floorf((v + GOFF) * INVH);
    return min(GD - 1, max(0, c));
}
__device__ __forceinline__ u64 bitrange(int lo, int hi) {
    return (~0ull << lo) & (~0ull >> (63 - hi));
}

// ---------------------------------------------------------------------------
__global__ void zero_k() {
    int i = blockIdx.x * blockDim.x + threadIdx.x;
    if (i < NC) { g_count[i] = 0; g_count0[i] = 0; }
    if (i < GD * GD) { g_occ[i] = 0; g_occX[i] = 0; }
    if (i < GD) g_occP[i] = 0;
}

__global__ void count_k(const float* __restrict__ pc1,
                        const float* __restrict__ pc0) {
    int i = blockIdx.x * blockDim.x + threadIdx.x;
    {
        float x = pc1[3 * i], y = pc1[3 * i + 1], z = pc1[3 * i + 2];
        int cx = cellc(x), cy = cellc(y), cz = cellc(z);
        atomicAdd(&g_count[(cz * GD + cy) * GD + cx], 1);
        atomicOr(&g_occ [cz * GD + cy], 1ull << cx);
        atomicOr(&g_occX[cz * GD + cx], 1ull << cy);
    }
    {
        float x = pc0[3 * i], y = pc0[3 * i + 1], z = pc0[3 * i + 2];
        atomicAdd(&g_count0[(cellc(z) * GD + cellc(y)) * GD + cellc(x)], 1);
    }
}

// --- 3-phase exclusive scan, both grids via grid.y / grid.x ---
__global__ void scan_a() {
    int which = blockIdx.y;
    int* cnt = which ? g_count0 : g_count;
    int t = threadIdx.x;
    int base = (blockIdx.x * 256 + t) * 4;
    int s = cnt[base] + cnt[base + 1] + cnt[base + 2] + cnt[base + 3];
    __shared__ int sh[256];
    sh[t] = s; __syncthreads();
    for (int o = 1; o < 256; o <<= 1) {
        int u = (t >= o) ? sh[t - o] : 0; __syncthreads();
        sh[t] += u; __syncthreads();
    }
    if (t == 255) g_bsum[which][blockIdx.x] = sh[255];
}

// blocks 0,1: block-sum scans; block 2: build g_occP from g_occ
__global__ void scan_b() {
    int t = threadIdx.x;
    if (blockIdx.x == 2) {
        int z = t >> 2, q = t & 3;
        u64 w = 0;
        for (int y = q * 16; y < q * 16 + 16; y++)
            if (g_occ[z * GD + y]) w |= 1ull << y;
        if (w) atomicOr(&g_occP[z], w);
        return;
    }
    int which = blockIdx.x;
    __shared__ int sh[256];
    int v = g_bsum[which][t];
    sh[t] = v; __syncthreads();
    for (int o = 1; o < 256; o <<= 1) {
        int u = (t >= o) ? sh[t - o] : 0; __syncthreads();
        sh[t] += u; __syncthreads();
    }
    g_bsum[which][t] = sh[t] - v;
}

__global__ void scan_c() {
    int which = blockIdx.y;
    int* cnt = which ? g_count0  : g_count;
    int* off = which ? g_off0    : g_off;
    int* cur = which ? g_cursor0 : g_cursor;
    int t = threadIdx.x;
    int base = (blockIdx.x * 256 + t) * 4;
    int c0 = cnt[base], c1 = cnt[base + 1];
    int c2 = cnt[base + 2], c3 = cnt[base + 3];
    int s = c0 + c1 + c2 + c3;
    __shared__ int sh[256];
    sh[t] = s; __syncthreads();
    for (int o = 1; o < 256; o <<= 1) {
        int u = (t >= o) ? sh[t - o] : 0; __syncthreads();
        sh[t] += u; __syncthreads();
    }
    int o0 = sh[t] - s + g_bsum[which][blockIdx.x];
    int o1 = o0 + c0, o2 = o1 + c1, o3 = o2 + c2;
    off[base] = o0;     off[base + 1] = o1;
    off[base + 2] = o2; off[base + 3] = o3;
    cur[base] = o0;     cur[base + 1] = o1;
    cur[base + 2] = o2; cur[base + 3] = o3;
    if (blockIdx.x == 0 && t == 0) off[NC] = NPTS;
}

__global__ void scatter_k(const float* __restrict__ pc1,
                          const float* __restrict__ pc0) {
    int i = blockIdx.x * blockDim.x + threadIdx.x;
    {
        float x = pc1[3 * i], y = pc1[3 * i + 1], z = pc1[3 * i + 2];
        int c = (cellc(z) * GD + cellc(y)) * GD + cellc(x);
        int idx = atomicAdd(&g_cursor[c], 1);
        g_pts[idx] = make_float4(x, y, z, x * x + y * y + z * z);
    }
    {
        float x = pc0[3 * i], y = pc0[3 * i + 1], z = pc0[3 * i + 2];
        int c = (cellc(z) * GD + cellc(y)) * GD + cellc(x);
        int idx = atomicAdd(&g_cursor0[c], 1);
        g_pts0[idx] = make_float4(x, y, z, fmaf(x, x, fmaf(y, y, z * z)));
    }
}

// ---------------------------------------------------------------------------
// Search: 8 lanes per sorted pc0 point. Uniform traversal within the group
// (mask/offset loads broadcast); candidates in a run split lane-cyclically
// (coalesced 128B sectors). Per-shell group min via group-local shfl_xor;
// the 8 group lanes are always converged (uniform bounds, shared break).
// ---------------------------------------------------------------------------
__global__ void __launch_bounds__(ST) search_k() {
    int t = threadIdx.x;
    int gid = blockIdx.x * ST + t;
    int i = gid / W;                         // point index
    int l = gid & (W - 1);                   // lane within group
    unsigned gm = 0xFFu << ((t & 31) & ~(W - 1));  // group-local shuffle mask

    float4 a = __ldg(&g_pts0[i]);
    float nax = -2.f * a.x, nay = -2.f * a.y, naz = -2.f * a.z;
    float asq = a.w;
    int cx = cellc(a.x), cy = cellc(a.y), cz = cellc(a.z);

    float c0a = 1e30f, c1a = 1e30f;

    auto scan_run = [&](int cc0, int cc1) {
        int s = __ldg(&g_off[cc0]);          // uniform in group -> broadcast
        int e = __ldg(&g_off[cc1 + 1]);
        int k = s + l;
        for (; k + W < e; k += 2 * W) {
            float4 p0 = __ldg(&g_pts[k]);
            float4 p1 = __ldg(&g_pts[k + W]);
            c0a = fminf(c0a, fmaf(nax, p0.x, fmaf(nay, p0.y, fmaf(naz, p0.z, p0.w))));
            c1a = fminf(c1a, fmaf(nax, p1.x, fmaf(nay, p1.y, fmaf(naz, p1.z, p1.w))));
        }
        if (k < e) {
            float4 p = __ldg(&g_pts[k]);
            c0a = fminf(c0a, fmaf(nax, p.x, fmaf(nay, p.y, fmaf(naz, p.z, p.w))));
        }
    };

    float m = 1e30f;
    for (int r = 0; r <= 12; r++) {
        int z0 = max(cz - r, 0), z1 = min(cz + r, GD - 1);
        int y0 = max(cy - r, 0), y1 = min(cy + r, GD - 1);
        int xl = cx - r, xr = cx + r;
        int x0 = max(xl, 0), x1 = min(xr, GD - 1);
        u64 xm = bitrange(x0, x1);

        for (int z = z0; z <= z1; z++) {
            int zb = z * GD;
            bool zedge = (z == cz - r) || (z == cz + r);
            if (zedge) {
                u64 wp = __ldg(&g_occP[z]) & bitrange(y0, y1);
                while (wp) {
                    int y = __ffsll((long long)wp) - 1; wp &= wp - 1;
                    u64 w = __ldg(&g_occ[zb + y]) & xm;
                    if (w) {
                        int lo = __ffsll((long long)w) - 1;
                        int hi = 63 - __clzll(w);
                        scan_run((zb + y) * GD + lo, (zb + y) * GD + hi);
                    }
                }
            } else {
                int yl = cy - r, yr2 = cy + r;
                if (yl >= 0) {
                    u64 w = __ldg(&g_occ[zb + yl]) & xm;
                    if (w) {
                        int lo = __ffsll((long long)w) - 1;
                        int hi = 63 - __clzll(w);
                        scan_run((zb + yl) * GD + lo, (zb + yl) * GD + hi);
                    }
                }
                if (yr2 <= GD - 1) {
                    u64 w = __ldg(&g_occ[zb + yr2]) & xm;
                    if (w) {
                        int lo = __ffsll((long long)w) - 1;
                        int hi = 63 - __clzll(w);
                        scan_run((zb + yr2) * GD + lo, (zb + yr2) * GD + hi);
                    }
                }
                int yi0 = max(yl + 1, 0), yi1 = min(yr2 - 1, GD - 1);
                if (yi0 <= yi1) {
                    u64 ym = bitrange(yi0, yi1);
                    if (xl >= 0) {
                        u64 wc = __ldg(&g_occX[zb + xl]) & ym;
                        while (wc) {
                            int y = __ffsll((long long)wc) - 1; wc &= wc - 1;
                            int c = (zb + y) * GD + xl;
                            scan_run(c, c);
                        }
                    }
                    if (xr <= GD - 1) {
                        u64 wc = __ldg(&g_occX[zb + xr]) & ym;
                        while (wc) {
                            int y = __ffsll((long long)wc) - 1; wc &= wc - 1;
                            int c = (zb + y) * GD + xr;
                            scan_run(c, c);
                        }
                    }
                }
            }
        }
        // group min (lanes of a group always converged here)
        float ml = fminf(c0a, c1a);
        ml = fminf(ml, __shfl_xor_sync(gm, ml, 1));
        ml = fminf(ml, __shfl_xor_sync(gm, ml, 2));
        ml = fminf(ml, __shfl_xor_sync(gm, ml, 4));
        m = ml;
        float rh = r * H;
        float rh2 = rh * rh;
        if (m + asq <= rh2 || rh2 > 2.0f) break;   // unscanned have d >= rh2
    }

    float d = m + asq;
    float s = 0.f, c = 0.f;
    if (l == 0 && d <= 2.0f) { s = d; c = 1.f; }   // one lane per point counts

    __shared__ float ss[ST], sc[ST];
    ss[t] = s; sc[t] = c;
    __syncthreads();
    for (int o = ST / 2; o > 0; o >>= 1) {
        if (t < o) { ss[t] += ss[t + o]; sc[t] += sc[t + o]; }
        __syncthreads();
    }
    if (t == 0) {
        g_block[2 * blockIdx.x + 0] = ss[0];
        g_block[2 * blockIdx.x + 1] = sc[0];
    }
}

// ---------------------------------------------------------------------------
// Final: reduce SB=4096 block partials with 256 threads (16 each)
__global__ void final_k(float* __restrict__ out) {
    int t = threadIdx.x;
    float s = 0.f, c = 0.f;
#pragma unroll
    for (int k = 0; k < SB / 256; k++) {
        s += g_block[2 * (t + k * 256) + 0];
        c += g_block[2 * (t + k * 256) + 1];
    }
    __shared__ float ss[256], sc[256];
    ss[t] = s; sc[t] = c;
    __syncthreads();
    for (int o = 128; o > 0; o >>= 1) {
        if (t < o) { ss[t] += ss[t + o]; sc[t] += sc[t + o]; }
        __syncthreads();
    }
    if (t == 0) out[0] = ss[0] / sc[0];
}

extern "C" void kernel_launch(void* const* d_in, const int* in_sizes, int n_in,
                              void* d_out, int out_size) {
    const float* pc0 = (const float*)d_in[0];
    const float* pc1 = (const float*)d_in[1];
    (void)in_sizes; (void)n_in; (void)out_size;

    zero_k   <<<NC / 256, 256>>>();
    count_k  <<<NPTS / 256, 256>>>(pc1, pc0);
    scan_a   <<<dim3(256, 2), 256>>>();
    scan_b   <<<3, 256>>>();
    scan_c   <<<dim3(256, 2), 256>>>();
    scatter_k<<<NPTS / 256, 256>>>(pc1, pc0);
    search_k <<<SB, ST>>>();
    final_k  <<<1, 256>>>((float*)d_out);
}